// round 12
// baseline (speedup 1.0000x reference)
#include <cuda_runtime.h>
#include <cuda_fp16.h>
#include <cstdint>
#include <cstddef>

#define T_ 2048
#define H_ 1024
#define F_ 512
#define E_ 32
#define K_ 4
#define NSLOT (T_*K_)
#define SLOTPAD (NSLOT+128)
#define MAXTILES 96

#define RSTRIDE 144            // bytes per smem row (64 halves + 8 pad)
#define STG_B   36864          // A 128*144 + B 128*144
#define BOFF_B  18432
#define GSMEM   (3*STG_B)      // 110592, 3-stage

// ---------------- scratch ----------------
__device__ int    g_cnt[E_];
__device__ int    g_off[E_+1];
__device__ int    g_sel[NSLOT];
__device__ float  g_wgt[NSLOT];
__device__ int    g_slotTok[SLOTPAD];
__device__ float  g_slotW[SLOTPAD];
__device__ int    g_tileE[MAXTILES];
__device__ int    g_tileM[MAXTILES];
__device__ __half g_WGh[(size_t)E_*F_*H_];
__device__ __half g_WUh[(size_t)E_*F_*H_];
__device__ __half g_WDh[(size_t)E_*H_*F_];
__device__ __half g_Xh [(size_t)T_*H_];
__device__ __half g_Hbuf16[(size_t)SLOTPAD*F_];   // gate, then h=relu(g)*u in place

// ---------------- helpers ----------------
__device__ __forceinline__ uint32_t smem_u32(const void* p){
    uint32_t a; asm("{ .reg .u64 t; cvta.to.shared.u64 t, %1; cvt.u32.u64 %0, t; }" : "=r"(a) : "l"(p));
    return a;
}
__device__ __forceinline__ void cpa16(uint32_t dst, const void* src){
    asm volatile("cp.async.cg.shared.global [%0], [%1], 16;" :: "r"(dst), "l"(src) : "memory");
}
#define CP_COMMIT() asm volatile("cp.async.commit_group;" ::: "memory")
#define CP_WAIT1()  asm volatile("cp.async.wait_group 1;" ::: "memory")

__device__ __forceinline__ void mma_f16(float* c, uint32_t a0,uint32_t a1,uint32_t a2,uint32_t a3,
                                        uint32_t b0,uint32_t b1){
    asm("mma.sync.aligned.m16n8k16.row.col.f32.f16.f16.f32 "
        "{%0,%1,%2,%3},{%4,%5,%6,%7},{%8,%9},{%0,%1,%2,%3};"
        : "+f"(c[0]),"+f"(c[1]),"+f"(c[2]),"+f"(c[3])
        : "r"(a0),"r"(a1),"r"(a2),"r"(a3),"r"(b0),"r"(b1));
}
__device__ __forceinline__ void ldsm4(uint32_t& r0,uint32_t& r1,uint32_t& r2,uint32_t& r3,
                                      uint32_t addr){
    asm volatile("ldmatrix.sync.aligned.m8n8.x4.shared.b16 {%0,%1,%2,%3}, [%4];"
        : "=r"(r0),"=r"(r1),"=r"(r2),"=r"(r3) : "r"(addr));
}

// ---------------- 1. fused convert(WG,WU,X) + router ------------------------
__global__ __launch_bounds__(256) void cvtrouter(const float4* __restrict__ wg,
                                                 const float4* __restrict__ wu,
                                                 const float4* __restrict__ hs,
                                                 const float* __restrict__ RI,
                                                 const float* __restrict__ WR,
                                                 float* __restrict__ logits){
    if (blockIdx.x < 128){
        int gid = blockIdx.x*256 + threadIdx.x;
        int warp = gid >> 5, lane = gid & 31;
        int t0 = warp*2;
        const float* xa = RI + (size_t)t0*H_;
        const float* xb = RI + (size_t)(t0+1)*H_;
        float4 ra[8], rb[8];
        #pragma unroll
        for (int j=0;j<8;j++){ ra[j] = *(const float4*)&xa[j*128 + lane*4];
                               rb[j] = *(const float4*)&xb[j*128 + lane*4]; }
        float l0 = 0.f, l1 = 0.f;
        for (int e=0;e<E_;e++){
            const float* w = WR + (size_t)e*H_;
            float s0=0.f, s1=0.f;
            #pragma unroll
            for (int j=0;j<8;j++){
                float4 wv = *(const float4*)&w[j*128 + lane*4];
                s0 += ra[j].x*wv.x + ra[j].y*wv.y + ra[j].z*wv.z + ra[j].w*wv.w;
                s1 += rb[j].x*wv.x + rb[j].y*wv.y + rb[j].z*wv.z + rb[j].w*wv.w;
            }
            #pragma unroll
            for (int off=16;off;off>>=1){
                s0 += __shfl_xor_sync(0xffffffffu, s0, off);
                s1 += __shfl_xor_sync(0xffffffffu, s1, off);
            }
            if (lane == e){ l0 = s0; l1 = s1; }
        }
        logits[(size_t)t0*E_ + lane]     = l0;
        logits[(size_t)(t0+1)*E_ + lane] = l1;
        #pragma unroll
        for (int tok=0; tok<2; tok++){
            int t = t0 + tok;
            float cur = (tok==0) ? l0 : l1;
            int idx = lane;
            float vsel[K_]; int isel[K_];
            #pragma unroll
            for (int k=0;k<K_;k++){
                float bv = cur; int bi = idx;
                #pragma unroll
                for (int off=16;off;off>>=1){
                    float ov = __shfl_xor_sync(0xffffffffu, bv, off);
                    int   oi = __shfl_xor_sync(0xffffffffu, bi, off);
                    if (ov > bv || (ov == bv && oi < bi)){ bv = ov; bi = oi; }
                }
                vsel[k]=bv; isel[k]=bi;
                if (idx == bi) cur = -__int_as_float(0x7f800000);
            }
            float mx = vsel[0], den = 0.f, w[K_];
            #pragma unroll
            for (int k=0;k<K_;k++){ w[k] = expf(vsel[k]-mx); den += w[k]; }
            if (lane < K_){
                g_sel[t*K_+lane] = isel[lane];
                g_wgt[t*K_+lane] = w[lane]/den;
                atomicAdd(&g_cnt[isel[lane]], 1);
            }
        }
        return;
    }
    const int NW = E_*F_*H_/8;
    const int NX = T_*H_/8;
    long c0 = ((long)(blockIdx.x-128)*256 + threadIdx.x)*4;
    if (c0 >= 2L*NW + NX) return;
    const float4* src; uint4* dst; long base;
    if      (c0 <    NW){ src=wg; dst=(uint4*)g_WGh; base=0; }
    else if (c0 < 2L*NW){ src=wu; dst=(uint4*)g_WUh; base=NW; }
    else                { src=hs; dst=(uint4*)g_Xh;  base=2L*NW; }
    long i = c0 - base;
    float4 a[8];
    #pragma unroll
    for (int j=0;j<8;j++) a[j] = src[2*i + j];
    #pragma unroll
    for (int j=0;j<4;j++){
        uint4 o;
        ((__half2*)&o)[0] = __floats2half2_rn(a[2*j].x,   a[2*j].y);
        ((__half2*)&o)[1] = __floats2half2_rn(a[2*j].z,   a[2*j].w);
        ((__half2*)&o)[2] = __floats2half2_rn(a[2*j+1].x, a[2*j+1].y);
        ((__half2*)&o)[3] = __floats2half2_rn(a[2*j+1].z, a[2*j+1].w);
        dst[i+j] = o;
    }
}

// ---------------- 2. scan + scatter + tile table (one block) ----------------
__global__ __launch_bounds__(256) void scanscatter(){
    __shared__ int soff[E_];
    __shared__ int spos[E_];
    int tid = threadIdx.x;
    if (tid < E_) spos[tid] = 0;
    if (tid == 0){
        int acc = 0;
        for (int e=0;e<E_;e++){ soff[e]=acc; g_off[e]=acc; acc += g_cnt[e]; }
        g_off[E_] = acc;
        int tt = 0;
        for (int e=0;e<E_;e++){
            int nt = (g_cnt[e]+127)>>7;
            for (int i=0;i<nt;i++){ g_tileE[tt]=e; g_tileM[tt]=i; tt++; }
        }
        for (; tt<MAXTILES; tt++) g_tileE[tt] = -1;
    }
    __syncthreads();
    for (int idx = tid; idx < NSLOT; idx += 256){
        int e = g_sel[idx];
        int slot = soff[e] + atomicAdd(&spos[e], 1);
        g_slotTok[slot] = idx >> 2;
        g_slotW[slot]   = g_wgt[idx];
    }
}

// ---------------- 3. unified GEMM: 128x128 block, 64x32 warp tiles ----------
// MODE 0: gate  -> fp16 to Hbuf (+WD convert piggyback)
// MODE 1: up    -> h = relu(gate)*up in-place in Hbuf
// MODE 2: down  -> atomicAdd wsc*C into out
template<int KDIM, int MODE>
__global__ __launch_bounds__(256,2) void gemm16(float* __restrict__ outf,
                                                const float4* __restrict__ wdsrc){
    extern __shared__ char smem[];
    int tile = blockIdx.y;
    if (MODE==0 && tile >= MAXTILES){
        long cb = (long)(tile - MAXTILES)*4 + blockIdx.x;
        long i  = (cb*256 + threadIdx.x)*4;
        float4 a[8];
        #pragma unroll
        for (int j=0;j<8;j++) a[j] = wdsrc[2*i + j];
        uint4* dst = (uint4*)g_WDh;
        #pragma unroll
        for (int j=0;j<4;j++){
            uint4 o;
            ((__half2*)&o)[0] = __floats2half2_rn(a[2*j].x,   a[2*j].y);
            ((__half2*)&o)[1] = __floats2half2_rn(a[2*j].z,   a[2*j].w);
            ((__half2*)&o)[2] = __floats2half2_rn(a[2*j+1].x, a[2*j+1].y);
            ((__half2*)&o)[3] = __floats2half2_rn(a[2*j+1].z, a[2*j+1].w);
            dst[i+j] = o;
        }
        return;
    }
    int e = g_tileE[tile];
    if (e < 0) return;
    int n0 = blockIdx.x*128;
    int m0 = g_tileM[tile]*128;
    int base = g_off[e];
    int Me   = g_off[e+1] - base;
    int tid = threadIdx.x, lane = tid&31, wid = tid>>5;
    uint32_t sb = smem_u32(smem);

    const __half* Abase = (MODE<2) ? g_Xh : g_Hbuf16;
    const __half* Wbase = (MODE==0) ? g_WGh : (MODE==1) ? g_WUh : g_WDh;
    const int WROWS = (MODE==2) ? H_ : F_;

    // producers: A 1024 chunks (4/thread), B 1024 chunks (4/thread)
    const __half* srcA[4]; uint32_t dofA[4];
    const __half* srcB[4]; uint32_t dofB[4];
    #pragma unroll
    for (int i=0;i<4;i++){
        int c = tid + i*256, row = c>>3, ch = c&7;
        int arow = (MODE<2) ? g_slotTok[base + m0 + row] : (base + m0 + row);
        srcA[i] = Abase + (size_t)arow*KDIM + ch*8;
        dofA[i] = (uint32_t)row*RSTRIDE + ch*16;
        srcB[i] = Wbase + (size_t)e*WROWS*KDIM + (size_t)(n0+row)*KDIM + ch*8;
        dofB[i] = dofA[i];
    }

    const int NKT = KDIM/64;
    #pragma unroll
    for (int kt=0; kt<2; kt++){
        uint32_t s0 = sb + kt*STG_B;
        #pragma unroll
        for (int i=0;i<4;i++){
            cpa16(s0 + dofA[i], srcA[i] + kt*64);
            cpa16(s0 + BOFF_B + dofB[i], srcB[i] + kt*64);
        }
        CP_COMMIT();
    }

    int g = lane>>2, tg = lane&3;
    int wm = wid&1, wn = wid>>1;
    uint32_t aOff = (uint32_t)(wm*64 + (lane&7) + ((lane>>3)&1)*8)*RSTRIDE + ((lane>>4)&1)*16;
    uint32_t bOff = (uint32_t)(wn*32 + (lane&7) + ((lane>>4)&1)*8)*RSTRIDE + ((lane>>3)&1)*16;

    float acc[4][4][4] = {};

    for (int kt=0; kt<NKT; kt++){
        CP_WAIT1();
        __syncthreads();
        if (kt+2 < NKT){
            uint32_t s0 = sb + ((kt+2)%3)*STG_B;
            int ko = (kt+2)*64;
            #pragma unroll
            for (int i=0;i<4;i++){
                cpa16(s0 + dofA[i], srcA[i] + ko);
                cpa16(s0 + BOFF_B + dofB[i], srcB[i] + ko);
            }
        }
        CP_COMMIT();
        int s = kt - (kt/3)*3;
        uint32_t sA = sb + s*STG_B;
        uint32_t sB = sA + BOFF_B;
        #pragma unroll
        for (int ks=0; ks<4; ks++){
            uint32_t af[16], bf[8];
            #pragma unroll
            for (int mt=0; mt<4; mt++)
                ldsm4(af[mt*4],af[mt*4+1],af[mt*4+2],af[mt*4+3],
                      sA + aOff + mt*16*RSTRIDE + ks*32);
            ldsm4(bf[0],bf[1],bf[2],bf[3], sB + bOff + ks*32);
            ldsm4(bf[4],bf[5],bf[6],bf[7], sB + bOff + 16*RSTRIDE + ks*32);
            #pragma unroll
            for (int nf=0; nf<4; nf++)
                #pragma unroll
                for (int mt=0; mt<4; mt++)
                    mma_f16(acc[mt][nf], af[mt*4],af[mt*4+1],af[mt*4+2],af[mt*4+3],
                            bf[nf*2],bf[nf*2+1]);
        }
    }

    #pragma unroll
    for (int mt=0; mt<4; mt++){
        #pragma unroll
        for (int half=0; half<2; half++){
            int r = wm*64 + mt*16 + half*8 + g;
            if (m0 + r < Me){
                if (MODE == 0){
                    size_t ob = (size_t)(base+m0+r)*F_ + n0;
                    #pragma unroll
                    for (int nf=0; nf<4; nf++){
                        int col = wn*32 + nf*8 + 2*tg;
                        *(__half2*)&g_Hbuf16[ob + col] =
                            __floats2half2_rn(acc[mt][nf][half*2], acc[mt][nf][half*2+1]);
                    }
                } else if (MODE == 1){
                    size_t ob = (size_t)(base+m0+r)*F_ + n0;
                    #pragma unroll
                    for (int nf=0; nf<4; nf++){
                        int col = wn*32 + nf*8 + 2*tg;
                        __half2 gv = *(__half2*)&g_Hbuf16[ob + col];
                        float g0 = fmaxf(__half2float(__low2half(gv)), 0.f);
                        float g1 = fmaxf(__half2float(__high2half(gv)), 0.f);
                        *(__half2*)&g_Hbuf16[ob + col] =
                            __floats2half2_rn(g0*acc[mt][nf][half*2], g1*acc[mt][nf][half*2+1]);
                    }
                } else {
                    float wsc = g_slotW[base+m0+r];
                    int   tok = g_slotTok[base+m0+r];
                    float* orow = outf + (size_t)tok*H_ + n0;
                    #pragma unroll
                    for (int nf=0; nf<4; nf++){
                        int col = wn*32 + nf*8 + 2*tg;
                        atomicAdd(&orow[col  ], acc[mt][nf][half*2  ]*wsc);
                        atomicAdd(&orow[col+1], acc[mt][nf][half*2+1]*wsc);
                    }
                }
            }
        }
    }
}

// ---------------- launch ----------------------------------------------------
extern "C" void kernel_launch(void* const* d_in, const int* in_sizes, int n_in,
                              void* d_out, int out_size){
    const float* RI = (const float*)d_in[0];
    const float* HS = (const float*)d_in[1];
    const float* WR = (const float*)d_in[2];
    const float* WG = (const float*)d_in[3];
    const float* WU = (const float*)d_in[4];
    const float* WD = (const float*)d_in[5];
    float* out    = (float*)d_out;
    float* logits = out + (size_t)T_*H_;

    cudaFuncSetAttribute(gemm16<1024,0>, cudaFuncAttributeMaxDynamicSharedMemorySize, GSMEM);
    cudaFuncSetAttribute(gemm16<1024,1>, cudaFuncAttributeMaxDynamicSharedMemorySize, GSMEM);
    cudaFuncSetAttribute(gemm16<512, 2>, cudaFuncAttributeMaxDynamicSharedMemorySize, GSMEM);

    void* cntp; cudaGetSymbolAddress(&cntp, g_cnt);
    cudaMemsetAsync(out, 0, (size_t)T_*H_*sizeof(float));
    cudaMemsetAsync(cntp, 0, E_*sizeof(int));

    cvtrouter     <<<128+4352, 256>>>((const float4*)WG, (const float4*)WU,
                                      (const float4*)HS, RI, WR, logits);
    scanscatter   <<<1, 256>>>();
    // gate: x = F/128 = 4; extra y blocks convert WD (2048 blocks / 4 per y)
    gemm16<1024,0><<<dim3(F_/128, MAXTILES+512), 256, GSMEM>>>(nullptr, (const float4*)WD);
    gemm16<1024,1><<<dim3(F_/128, MAXTILES),     256, GSMEM>>>(nullptr, nullptr);
    gemm16<512, 2><<<dim3(H_/128, MAXTILES),     256, GSMEM>>>(out, nullptr);
}

// round 13
// speedup vs baseline: 1.0416x; 1.0416x over previous
#include <cuda_runtime.h>
#include <cuda_fp16.h>
#include <cstdint>
#include <cstddef>

#define T_ 2048
#define H_ 1024
#define F_ 512
#define E_ 32
#define K_ 4
#define NSLOT (T_*K_)
#define SLOTPAD (NSLOT+128)
#define MAXTILES 96

#define RSTRIDE 80             // bytes per smem row (32 halves + 8 pad)
#define STG_B   15360          // A 128*80 + B 64*80
#define BOFF_B  10240
#define GSMEM   (3*STG_B)      // 46080, 3-stage

// ---------------- scratch ----------------
__device__ int    g_cnt[E_];
__device__ int    g_off[E_+1];
__device__ int    g_sel[NSLOT];
__device__ float  g_wgt[NSLOT];
__device__ int    g_slotTok[SLOTPAD];
__device__ float  g_slotW[SLOTPAD];
__device__ int    g_tileE[MAXTILES];
__device__ int    g_tileM[MAXTILES];
__device__ __half g_WGh[(size_t)E_*F_*H_];
__device__ __half g_WUh[(size_t)E_*F_*H_];
__device__ __half g_WDh[(size_t)E_*H_*F_];
__device__ __half g_Xh [(size_t)T_*H_];
__device__ __half g_Hbuf16[(size_t)SLOTPAD*F_];   // gate, then h=relu(g)*u in place

// ---------------- helpers ----------------
__device__ __forceinline__ uint32_t smem_u32(const void* p){
    uint32_t a; asm("{ .reg .u64 t; cvta.to.shared.u64 t, %1; cvt.u32.u64 %0, t; }" : "=r"(a) : "l"(p));
    return a;
}
__device__ __forceinline__ void cpa16(uint32_t dst, const void* src){
    asm volatile("cp.async.cg.shared.global [%0], [%1], 16;" :: "r"(dst), "l"(src) : "memory");
}
#define CP_COMMIT() asm volatile("cp.async.commit_group;" ::: "memory")
#define CP_WAIT1()  asm volatile("cp.async.wait_group 1;" ::: "memory")

__device__ __forceinline__ void mma_f16(float* c, uint32_t a0,uint32_t a1,uint32_t a2,uint32_t a3,
                                        uint32_t b0,uint32_t b1){
    asm("mma.sync.aligned.m16n8k16.row.col.f32.f16.f16.f32 "
        "{%0,%1,%2,%3},{%4,%5,%6,%7},{%8,%9},{%0,%1,%2,%3};"
        : "+f"(c[0]),"+f"(c[1]),"+f"(c[2]),"+f"(c[3])
        : "r"(a0),"r"(a1),"r"(a2),"r"(a3),"r"(b0),"r"(b1));
}
__device__ __forceinline__ void ldsm4(uint32_t& r0,uint32_t& r1,uint32_t& r2,uint32_t& r3,
                                      uint32_t addr){
    asm volatile("ldmatrix.sync.aligned.m8n8.x4.shared.b16 {%0,%1,%2,%3}, [%4];"
        : "=r"(r0),"=r"(r1),"=r"(r2),"=r"(r3) : "r"(addr));
}
__device__ __forceinline__ void cvt_chunk4(const float4* __restrict__ src,
                                           uint4* __restrict__ dst, long i){
    float4 a[8];
    #pragma unroll
    for (int j=0;j<8;j++) a[j] = src[2*i + j];
    #pragma unroll
    for (int j=0;j<4;j++){
        uint4 o;
        ((__half2*)&o)[0] = __floats2half2_rn(a[2*j].x,   a[2*j].y);
        ((__half2*)&o)[1] = __floats2half2_rn(a[2*j].z,   a[2*j].w);
        ((__half2*)&o)[2] = __floats2half2_rn(a[2*j+1].x, a[2*j+1].y);
        ((__half2*)&o)[3] = __floats2half2_rn(a[2*j+1].z, a[2*j+1].w);
        dst[i+j] = o;
    }
}

// ---------------- 1. fused convert(WG,X) + router ---------------------------
__global__ __launch_bounds__(256) void cvtrouter(const float4* __restrict__ wg,
                                                 const float4* __restrict__ hs,
                                                 const float* __restrict__ RI,
                                                 const float* __restrict__ WR,
                                                 float* __restrict__ logits){
    if (blockIdx.x < 128){
        int gid = blockIdx.x*256 + threadIdx.x;
        int warp = gid >> 5, lane = gid & 31;
        int t0 = warp*2;
        const float* xa = RI + (size_t)t0*H_;
        const float* xb = RI + (size_t)(t0+1)*H_;
        float4 ra[8], rb[8];
        #pragma unroll
        for (int j=0;j<8;j++){ ra[j] = *(const float4*)&xa[j*128 + lane*4];
                               rb[j] = *(const float4*)&xb[j*128 + lane*4]; }
        float l0 = 0.f, l1 = 0.f;
        for (int e=0;e<E_;e++){
            const float* w = WR + (size_t)e*H_;
            float s0=0.f, s1=0.f;
            #pragma unroll
            for (int j=0;j<8;j++){
                float4 wv = *(const float4*)&w[j*128 + lane*4];
                s0 += ra[j].x*wv.x + ra[j].y*wv.y + ra[j].z*wv.z + ra[j].w*wv.w;
                s1 += rb[j].x*wv.x + rb[j].y*wv.y + rb[j].z*wv.z + rb[j].w*wv.w;
            }
            #pragma unroll
            for (int off=16;off;off>>=1){
                s0 += __shfl_xor_sync(0xffffffffu, s0, off);
                s1 += __shfl_xor_sync(0xffffffffu, s1, off);
            }
            if (lane == e){ l0 = s0; l1 = s1; }
        }
        logits[(size_t)t0*E_ + lane]     = l0;
        logits[(size_t)(t0+1)*E_ + lane] = l1;
        #pragma unroll
        for (int tok=0; tok<2; tok++){
            int t = t0 + tok;
            float cur = (tok==0) ? l0 : l1;
            int idx = lane;
            float vsel[K_]; int isel[K_];
            #pragma unroll
            for (int k=0;k<K_;k++){
                float bv = cur; int bi = idx;
                #pragma unroll
                for (int off=16;off;off>>=1){
                    float ov = __shfl_xor_sync(0xffffffffu, bv, off);
                    int   oi = __shfl_xor_sync(0xffffffffu, bi, off);
                    if (ov > bv || (ov == bv && oi < bi)){ bv = ov; bi = oi; }
                }
                vsel[k]=bv; isel[k]=bi;
                if (idx == bi) cur = -__int_as_float(0x7f800000);
            }
            float mx = vsel[0], den = 0.f, w[K_];
            #pragma unroll
            for (int k=0;k<K_;k++){ w[k] = expf(vsel[k]-mx); den += w[k]; }
            if (lane < K_){
                g_sel[t*K_+lane] = isel[lane];
                g_wgt[t*K_+lane] = w[lane]/den;
                atomicAdd(&g_cnt[isel[lane]], 1);
            }
        }
        return;
    }
    const int NW = E_*F_*H_/8;
    const int NX = T_*H_/8;
    long c0 = ((long)(blockIdx.x-128)*256 + threadIdx.x)*4;
    if (c0 >= (long)NW + NX) return;
    if (c0 < NW) cvt_chunk4(wg, (uint4*)g_WGh, c0);
    else         cvt_chunk4(hs, (uint4*)g_Xh,  c0 - NW);
}

// ---------------- 2. scan + scatter + tile table (one block) ----------------
__global__ __launch_bounds__(256) void scanscatter(){
    __shared__ int soff[E_];
    __shared__ int spos[E_];
    int tid = threadIdx.x;
    if (tid < E_) spos[tid] = 0;
    if (tid == 0){
        int acc = 0;
        for (int e=0;e<E_;e++){ soff[e]=acc; g_off[e]=acc; acc += g_cnt[e]; }
        g_off[E_] = acc;
        int tt = 0;
        for (int e=0;e<E_;e++){
            int nt = (g_cnt[e]+127)>>7;
            for (int i=0;i<nt;i++){ g_tileE[tt]=e; g_tileM[tt]=i; tt++; }
        }
        for (; tt<MAXTILES; tt++) g_tileE[tt] = -1;
    }
    __syncthreads();
    for (int idx = tid; idx < NSLOT; idx += 256){
        int e = g_sel[idx];
        int slot = soff[e] + atomicAdd(&spos[e], 1);
        g_slotTok[slot] = idx >> 2;
        g_slotW[slot]   = g_wgt[idx];
    }
}

// ---------------- 3. unified GEMM: 128x64 tile, k32, 3 blocks/SM ------------
// MODE 0: gate -> fp16 Hbuf   (piggyback: convert WU)
// MODE 1: up   -> relu(g)*u in-place Hbuf (piggyback: convert WD)
// MODE 2: down -> atomicAdd wsc*C into out
template<int KDIM, int MODE>
__global__ __launch_bounds__(256,3) void gemm16(float* __restrict__ outf,
                                                const float4* __restrict__ cvsrc,
                                                __half* __restrict__ cvdst){
    extern __shared__ char smem[];
    int tile = blockIdx.y;
    if (MODE<2 && tile >= MAXTILES){
        long cb = (long)(tile - MAXTILES)*8 + blockIdx.x;
        cvt_chunk4(cvsrc, (uint4*)cvdst, (cb*256 + threadIdx.x)*4);
        return;
    }
    int e = g_tileE[tile];
    if (e < 0) return;
    int n0 = blockIdx.x*64;
    int m0 = g_tileM[tile]*128;
    int base = g_off[e];
    int Me   = g_off[e+1] - base;
    int tid = threadIdx.x, lane = tid&31, wid = tid>>5;
    uint32_t sb = smem_u32(smem);

    const __half* Abase = (MODE<2) ? g_Xh : g_Hbuf16;
    const __half* Wbase = (MODE==0) ? g_WGh : (MODE==1) ? g_WUh : g_WDh;
    const int WROWS = (MODE==2) ? H_ : F_;

    // A: 512 chunks (128 rows x 4 chunks of 8 halves) -> 2/thread
    const __half* srcA[2]; uint32_t dofA[2];
    #pragma unroll
    for (int i=0;i<2;i++){
        int c = tid + i*256, row = c>>2, ch = c&3;
        int arow = (MODE<2) ? g_slotTok[base + m0 + row] : (base + m0 + row);
        srcA[i] = Abase + (size_t)arow*KDIM + ch*8;
        dofA[i] = (uint32_t)row*RSTRIDE + ch*16;
    }
    // B: 256 chunks -> 1/thread
    int rowB = tid>>2, chB = tid&3;
    const __half* srcB = Wbase + (size_t)e*WROWS*KDIM + (size_t)(n0+rowB)*KDIM + chB*8;
    uint32_t dofB = (uint32_t)rowB*RSTRIDE + chB*16;

    const int NKT = KDIM/32;
    #pragma unroll
    for (int kt=0; kt<2; kt++){
        uint32_t s0 = sb + kt*STG_B;
        cpa16(s0 + dofA[0], srcA[0] + kt*32);
        cpa16(s0 + dofA[1], srcA[1] + kt*32);
        cpa16(s0 + BOFF_B + dofB, srcB + kt*32);
        CP_COMMIT();
    }

    int g = lane>>2, tg = lane&3;
    int wm = wid&3, wn = wid>>2;
    uint32_t aOff = (uint32_t)(wm*32 + (lane&7) + ((lane>>3)&1)*8)*RSTRIDE + ((lane>>4)&1)*16;
    uint32_t bOff = (uint32_t)(wn*32 + (lane&7) + ((lane>>4)&1)*8)*RSTRIDE + ((lane>>3)&1)*16;

    float acc[2][4][4] = {};

    for (int kt=0; kt<NKT; kt++){
        CP_WAIT1();
        __syncthreads();
        if (kt+2 < NKT){
            uint32_t s0 = sb + ((kt+2)%3)*STG_B;
            int ko = (kt+2)*32;
            cpa16(s0 + dofA[0], srcA[0] + ko);
            cpa16(s0 + dofA[1], srcA[1] + ko);
            cpa16(s0 + BOFF_B + dofB, srcB + ko);
        }
        CP_COMMIT();
        int s = kt - (kt/3)*3;
        uint32_t sA = sb + s*STG_B;
        uint32_t sB = sA + BOFF_B;
        #pragma unroll
        for (int ks=0; ks<2; ks++){
            uint32_t a0[4], a1[4], bb[8];
            ldsm4(a0[0],a0[1],a0[2],a0[3], sA + aOff + ks*32);
            ldsm4(a1[0],a1[1],a1[2],a1[3], sA + aOff + 16*RSTRIDE + ks*32);
            ldsm4(bb[0],bb[1],bb[2],bb[3], sB + bOff + ks*32);
            ldsm4(bb[4],bb[5],bb[6],bb[7], sB + bOff + 16*RSTRIDE + ks*32);
            #pragma unroll
            for (int nf=0; nf<4; nf++){
                mma_f16(acc[0][nf], a0[0],a0[1],a0[2],a0[3], bb[nf*2],bb[nf*2+1]);
                mma_f16(acc[1][nf], a1[0],a1[1],a1[2],a1[3], bb[nf*2],bb[nf*2+1]);
            }
        }
    }

    #pragma unroll
    for (int mt=0; mt<2; mt++){
        #pragma unroll
        for (int half=0; half<2; half++){
            int r = wm*32 + mt*16 + half*8 + g;
            if (m0 + r < Me){
                if (MODE == 0){
                    size_t ob = (size_t)(base+m0+r)*F_ + n0;
                    #pragma unroll
                    for (int nf=0; nf<4; nf++){
                        int col = wn*32 + nf*8 + 2*tg;
                        *(__half2*)&g_Hbuf16[ob + col] =
                            __floats2half2_rn(acc[mt][nf][half*2], acc[mt][nf][half*2+1]);
                    }
                } else if (MODE == 1){
                    size_t ob = (size_t)(base+m0+r)*F_ + n0;
                    #pragma unroll
                    for (int nf=0; nf<4; nf++){
                        int col = wn*32 + nf*8 + 2*tg;
                        __half2 gv = *(__half2*)&g_Hbuf16[ob + col];
                        float g0 = fmaxf(__half2float(__low2half(gv)), 0.f);
                        float g1 = fmaxf(__half2float(__high2half(gv)), 0.f);
                        *(__half2*)&g_Hbuf16[ob + col] =
                            __floats2half2_rn(g0*acc[mt][nf][half*2], g1*acc[mt][nf][half*2+1]);
                    }
                } else {
                    float wsc = g_slotW[base+m0+r];
                    int   tok = g_slotTok[base+m0+r];
                    float* orow = outf + (size_t)tok*H_ + n0;
                    #pragma unroll
                    for (int nf=0; nf<4; nf++){
                        int col = wn*32 + nf*8 + 2*tg;
                        atomicAdd(&orow[col  ], acc[mt][nf][half*2  ]*wsc);
                        atomicAdd(&orow[col+1], acc[mt][nf][half*2+1]*wsc);
                    }
                }
            }
        }
    }
}

// ---------------- launch ----------------------------------------------------
extern "C" void kernel_launch(void* const* d_in, const int* in_sizes, int n_in,
                              void* d_out, int out_size){
    const float* RI = (const float*)d_in[0];
    const float* HS = (const float*)d_in[1];
    const float* WR = (const float*)d_in[2];
    const float* WG = (const float*)d_in[3];
    const float* WU = (const float*)d_in[4];
    const float* WD = (const float*)d_in[5];
    float* out    = (float*)d_out;
    float* logits = out + (size_t)T_*H_;

    cudaFuncSetAttribute(gemm16<1024,0>, cudaFuncAttributeMaxDynamicSharedMemorySize, GSMEM);
    cudaFuncSetAttribute(gemm16<1024,1>, cudaFuncAttributeMaxDynamicSharedMemorySize, GSMEM);
    cudaFuncSetAttribute(gemm16<512, 2>, cudaFuncAttributeMaxDynamicSharedMemorySize, GSMEM);

    __half *wuh, *wdh;
    cudaGetSymbolAddress((void**)&wuh, g_WUh);
    cudaGetSymbolAddress((void**)&wdh, g_WDh);
    void* cntp; cudaGetSymbolAddress(&cntp, g_cnt);
    cudaMemsetAsync(out, 0, (size_t)T_*H_*sizeof(float));
    cudaMemsetAsync(cntp, 0, E_*sizeof(int));

    // cvtrouter: 128 router blocks + (NW + NX)/1024 = 2304 convert blocks
    cvtrouter     <<<128+2304, 256>>>((const float4*)WG, (const float4*)HS,
                                      RI, WR, logits);
    scanscatter   <<<1, 256>>>();
    // gate: 8 x (96 tiles + 256 WU-convert rows)
    gemm16<1024,0><<<dim3(F_/64, MAXTILES+256), 256, GSMEM>>>(nullptr, (const float4*)WU, wuh);
    // up:   8 x (96 tiles + 256 WD-convert rows)
    gemm16<1024,1><<<dim3(F_/64, MAXTILES+256), 256, GSMEM>>>(nullptr, (const float4*)WD, wdh);
    gemm16<512, 2><<<dim3(H_/64, MAXTILES),     256, GSMEM>>>(out, nullptr, nullptr);
}

// round 14
// speedup vs baseline: 1.1271x; 1.0821x over previous
#include <cuda_runtime.h>
#include <cuda_fp16.h>
#include <cstdint>
#include <cstddef>

#define T_ 2048
#define H_ 1024
#define F_ 512
#define E_ 32
#define K_ 4
#define NSLOT (T_*K_)
#define SLOTPAD (NSLOT+128)
#define MAXTILES 96

#define RSTRIDE 80             // bytes per smem row (32 halves + 8 pad)
#define GU_STG  20480          // A 128*80 + G 64*80 + U 64*80
#define GU_GOFF 10240
#define GU_UOFF 15360
#define GU_SMEM (3*GU_STG)     // 61440
#define DN_STG  15360          // A 128*80 + B 64*80
#define DN_BOFF 10240
#define DN_SMEM (3*DN_STG)     // 46080

// ---------------- scratch ----------------
__device__ int    g_cnt[E_];
__device__ int    g_off[E_+1];
__device__ int    g_sel[NSLOT];
__device__ float  g_wgt[NSLOT];
__device__ int    g_slotTok[SLOTPAD];
__device__ float  g_slotW[SLOTPAD];
__device__ int    g_tileE[MAXTILES];
__device__ int    g_tileM[MAXTILES];
__device__ __half g_Xh [(size_t)T_*H_];
__device__ __half g_Hbuf16[(size_t)SLOTPAD*F_];

// ---------------- helpers ----------------
__device__ __forceinline__ uint32_t smem_u32(const void* p){
    uint32_t a; asm("{ .reg .u64 t; cvta.to.shared.u64 t, %1; cvt.u32.u64 %0, t; }" : "=r"(a) : "l"(p));
    return a;
}
__device__ __forceinline__ void cpa16(uint32_t dst, const void* src){
    asm volatile("cp.async.cg.shared.global [%0], [%1], 16;" :: "r"(dst), "l"(src) : "memory");
}
#define CP_COMMIT() asm volatile("cp.async.commit_group;" ::: "memory")
#define CP_WAIT1()  asm volatile("cp.async.wait_group 1;" ::: "memory")

__device__ __forceinline__ void mma_f16(float* c, uint32_t a0,uint32_t a1,uint32_t a2,uint32_t a3,
                                        uint32_t b0,uint32_t b1){
    asm("mma.sync.aligned.m16n8k16.row.col.f32.f16.f16.f32 "
        "{%0,%1,%2,%3},{%4,%5,%6,%7},{%8,%9},{%0,%1,%2,%3};"
        : "+f"(c[0]),"+f"(c[1]),"+f"(c[2]),"+f"(c[3])
        : "r"(a0),"r"(a1),"r"(a2),"r"(a3),"r"(b0),"r"(b1));
}
__device__ __forceinline__ void ldsm4(uint32_t& r0,uint32_t& r1,uint32_t& r2,uint32_t& r3,
                                      uint32_t addr){
    asm volatile("ldmatrix.sync.aligned.m8n8.x4.shared.b16 {%0,%1,%2,%3}, [%4];"
        : "=r"(r0),"=r"(r1),"=r"(r2),"=r"(r3) : "r"(addr));
}
__device__ __forceinline__ uint4 pack8(float4 a, float4 b){
    uint4 r;
    ((__half2*)&r)[0] = __floats2half2_rn(a.x, a.y);
    ((__half2*)&r)[1] = __floats2half2_rn(a.z, a.w);
    ((__half2*)&r)[2] = __floats2half2_rn(b.x, b.y);
    ((__half2*)&r)[3] = __floats2half2_rn(b.z, b.w);
    return r;
}

// ---------------- 1. router + X convert -------------------------------------
__global__ __launch_bounds__(256) void xrouter(const float4* __restrict__ hs,
                                               const float* __restrict__ RI,
                                               const float* __restrict__ WR,
                                               float* __restrict__ logits){
    if (blockIdx.x < 128){
        int gid = blockIdx.x*256 + threadIdx.x;
        int warp = gid >> 5, lane = gid & 31;
        int t0 = warp*2;
        const float* xa = RI + (size_t)t0*H_;
        const float* xb = RI + (size_t)(t0+1)*H_;
        float4 ra[8], rb[8];
        #pragma unroll
        for (int j=0;j<8;j++){ ra[j] = *(const float4*)&xa[j*128 + lane*4];
                               rb[j] = *(const float4*)&xb[j*128 + lane*4]; }
        float l0 = 0.f, l1 = 0.f;
        for (int e=0;e<E_;e++){
            const float* w = WR + (size_t)e*H_;
            float s0=0.f, s1=0.f;
            #pragma unroll
            for (int j=0;j<8;j++){
                float4 wv = *(const float4*)&w[j*128 + lane*4];
                s0 += ra[j].x*wv.x + ra[j].y*wv.y + ra[j].z*wv.z + ra[j].w*wv.w;
                s1 += rb[j].x*wv.x + rb[j].y*wv.y + rb[j].z*wv.z + rb[j].w*wv.w;
            }
            #pragma unroll
            for (int off=16;off;off>>=1){
                s0 += __shfl_xor_sync(0xffffffffu, s0, off);
                s1 += __shfl_xor_sync(0xffffffffu, s1, off);
            }
            if (lane == e){ l0 = s0; l1 = s1; }
        }
        logits[(size_t)t0*E_ + lane]     = l0;
        logits[(size_t)(t0+1)*E_ + lane] = l1;
        #pragma unroll
        for (int tok=0; tok<2; tok++){
            int t = t0 + tok;
            float cur = (tok==0) ? l0 : l1;
            int idx = lane;
            float vsel[K_]; int isel[K_];
            #pragma unroll
            for (int k=0;k<K_;k++){
                float bv = cur; int bi = idx;
                #pragma unroll
                for (int off=16;off;off>>=1){
                    float ov = __shfl_xor_sync(0xffffffffu, bv, off);
                    int   oi = __shfl_xor_sync(0xffffffffu, bi, off);
                    if (ov > bv || (ov == bv && oi < bi)){ bv = ov; bi = oi; }
                }
                vsel[k]=bv; isel[k]=bi;
                if (idx == bi) cur = -__int_as_float(0x7f800000);
            }
            float mx = vsel[0], den = 0.f, w[K_];
            #pragma unroll
            for (int k=0;k<K_;k++){ w[k] = expf(vsel[k]-mx); den += w[k]; }
            if (lane < K_){
                g_sel[t*K_+lane] = isel[lane];
                g_wgt[t*K_+lane] = w[lane]/den;
                atomicAdd(&g_cnt[isel[lane]], 1);
            }
        }
        return;
    }
    // X fp32 -> fp16: 262144 16B-chunks, 4/thread over 256 blocks
    long i = ((long)(blockIdx.x-128)*256 + threadIdx.x)*4;
    uint4* dst = (uint4*)g_Xh;
    float4 a[8];
    #pragma unroll
    for (int j=0;j<8;j++) a[j] = hs[2*i + j];
    #pragma unroll
    for (int j=0;j<4;j++) dst[i+j] = pack8(a[2*j], a[2*j+1]);
}

// ---------------- 2. scan + scatter + tile table (one block) ----------------
__global__ __launch_bounds__(256) void scanscatter(){
    __shared__ int soff[E_];
    __shared__ int spos[E_];
    int tid = threadIdx.x;
    if (tid < E_) spos[tid] = 0;
    if (tid == 0){
        int acc = 0;
        for (int e=0;e<E_;e++){ soff[e]=acc; g_off[e]=acc; acc += g_cnt[e]; }
        g_off[E_] = acc;
        int tt = 0;
        for (int e=0;e<E_;e++){
            int nt = (g_cnt[e]+127)>>7;
            for (int i=0;i<nt;i++){ g_tileE[tt]=e; g_tileM[tt]=i; tt++; }
        }
        for (; tt<MAXTILES; tt++) g_tileE[tt] = -1;
    }
    __syncthreads();
    for (int idx = tid; idx < NSLOT; idx += 256){
        int e = g_sel[idx];
        int slot = soff[e] + atomicAdd(&spos[e], 1);
        g_slotTok[slot] = idx >> 2;
        g_slotW[slot]   = g_wgt[idx];
    }
}

// ---------------- 3. gate+up GEMM: A cp.async fp16, B fp32-direct -----------
// 128x64 tile, k32 stages, 3-stage, single-sync; h = relu(g)*u -> Hbuf fp16
__global__ __launch_bounds__(256,2) void gateup_d(const float* __restrict__ WG,
                                                  const float* __restrict__ WU){
    extern __shared__ char smem[];
    int tile = blockIdx.y;
    int e = g_tileE[tile];
    if (e < 0) return;
    int n0 = blockIdx.x*64;
    int m0 = g_tileM[tile]*128;
    int base = g_off[e];
    int Me   = g_off[e+1] - base;
    int tid = threadIdx.x, lane = tid&31, wid = tid>>5;
    uint32_t sb = smem_u32(smem);

    // A: 512 fp16 chunks / 256 thr = 2/thread
    const __half* srcA[2]; uint32_t dofA[2];
    #pragma unroll
    for (int i=0;i<2;i++){
        int c = tid + i*256, row = c>>2, ch = c&3;
        srcA[i] = g_Xh + (size_t)g_slotTok[base + m0 + row]*H_ + ch*8;
        dofA[i] = (uint32_t)row*RSTRIDE + ch*16;
    }
    // B: 256 fp16-chunks per matrix = 1/thread; src fp32 (2 float4 per chunk)
    int rowB = tid>>2, chB = tid&3;
    const float* srcG = WG + (size_t)e*F_*H_ + (size_t)(n0+rowB)*H_ + chB*8;
    const float* srcU = WU + (size_t)e*F_*H_ + (size_t)(n0+rowB)*H_ + chB*8;
    uint32_t dofB = (uint32_t)rowB*RSTRIDE + chB*16;

    const int NKT = H_/32;   // 32
    // prologue
    float4 hg0,hg1,hu0,hu1;       // holdback: B tile kt+1
    {   // tile 0: LDG -> STS stage0
        float4 g0 = *(const float4*)(srcG), g1 = *(const float4*)(srcG+4);
        float4 u0 = *(const float4*)(srcU), u1 = *(const float4*)(srcU+4);
        *(uint4*)(smem + GU_GOFF + dofB) = pack8(g0,g1);
        *(uint4*)(smem + GU_UOFF + dofB) = pack8(u0,u1);
        // tile 1: hold
        hg0 = *(const float4*)(srcG+32); hg1 = *(const float4*)(srcG+36);
        hu0 = *(const float4*)(srcU+32); hu1 = *(const float4*)(srcU+36);
    }
    #pragma unroll
    for (int kt=0; kt<2; kt++){
        uint32_t s0 = sb + kt*GU_STG;
        cpa16(s0 + dofA[0], srcA[0] + kt*32);
        cpa16(s0 + dofA[1], srcA[1] + kt*32);
        CP_COMMIT();
    }

    int g = lane>>2, tg = lane&3;
    int wm = wid&3, wn = wid>>2;
    uint32_t aOff = (uint32_t)(wm*32 + (lane&7) + ((lane>>3)&1)*8)*RSTRIDE + ((lane>>4)&1)*16;
    uint32_t bOff = (uint32_t)(wn*32 + (lane&7) + ((lane>>4)&1)*8)*RSTRIDE + ((lane>>3)&1)*16;

    float accG[2][4][4] = {}; float accU[2][4][4] = {};

    for (int kt=0; kt<NKT; kt++){
        CP_WAIT1();
        __syncthreads();
        // STS held B tile (kt+1) into stage (kt+1)%3
        if (kt+1 < NKT){
            char* st = smem + ((kt+1)%3)*GU_STG;
            *(uint4*)(st + GU_GOFF + dofB) = pack8(hg0,hg1);
            *(uint4*)(st + GU_UOFF + dofB) = pack8(hu0,hu1);
        }
        // LDG B tile kt+2 into holdback
        if (kt+2 < NKT){
            int ko = (kt+2)*32;
            hg0 = *(const float4*)(srcG+ko); hg1 = *(const float4*)(srcG+ko+4);
            hu0 = *(const float4*)(srcU+ko); hu1 = *(const float4*)(srcU+ko+4);
        }
        // cp.async A tile kt+2
        if (kt+2 < NKT){
            uint32_t s0 = sb + ((kt+2)%3)*GU_STG;
            int ko = (kt+2)*32;
            cpa16(s0 + dofA[0], srcA[0] + ko);
            cpa16(s0 + dofA[1], srcA[1] + ko);
        }
        CP_COMMIT();
        int s = kt - (kt/3)*3;
        uint32_t sA = sb + s*GU_STG;
        uint32_t sG = sA + GU_GOFF;
        uint32_t sU = sA + GU_UOFF;
        #pragma unroll
        for (int ks=0; ks<2; ks++){
            uint32_t a0[4], a1[4], bg[8], bu[8];
            ldsm4(a0[0],a0[1],a0[2],a0[3], sA + aOff + ks*32);
            ldsm4(a1[0],a1[1],a1[2],a1[3], sA + aOff + 16*RSTRIDE + ks*32);
            ldsm4(bg[0],bg[1],bg[2],bg[3], sG + bOff + ks*32);
            ldsm4(bg[4],bg[5],bg[6],bg[7], sG + bOff + 16*RSTRIDE + ks*32);
            ldsm4(bu[0],bu[1],bu[2],bu[3], sU + bOff + ks*32);
            ldsm4(bu[4],bu[5],bu[6],bu[7], sU + bOff + 16*RSTRIDE + ks*32);
            #pragma unroll
            for (int nf=0; nf<4; nf++){
                mma_f16(accG[0][nf], a0[0],a0[1],a0[2],a0[3], bg[nf*2],bg[nf*2+1]);
                mma_f16(accG[1][nf], a1[0],a1[1],a1[2],a1[3], bg[nf*2],bg[nf*2+1]);
                mma_f16(accU[0][nf], a0[0],a0[1],a0[2],a0[3], bu[nf*2],bu[nf*2+1]);
                mma_f16(accU[1][nf], a1[0],a1[1],a1[2],a1[3], bu[nf*2],bu[nf*2+1]);
            }
        }
    }

    // epilogue: h = relu(g)*u -> fp16 Hbuf
    #pragma unroll
    for (int mt=0; mt<2; mt++){
        #pragma unroll
        for (int half=0; half<2; half++){
            int r = wm*32 + mt*16 + half*8 + g;
            if (m0 + r < Me){
                size_t ob = (size_t)(base+m0+r)*F_ + n0;
                #pragma unroll
                for (int nf=0; nf<4; nf++){
                    int col = wn*32 + nf*8 + 2*tg;
                    float h0 = fmaxf(accG[mt][nf][half*2  ],0.f)*accU[mt][nf][half*2  ];
                    float h1 = fmaxf(accG[mt][nf][half*2+1],0.f)*accU[mt][nf][half*2+1];
                    *(__half2*)&g_Hbuf16[ob + col] = __floats2half2_rn(h0,h1);
                }
            }
        }
    }
}

// ---------------- 4. down GEMM: A cp.async fp16 (Hbuf), B=WD fp32-direct ----
__global__ __launch_bounds__(256,2) void down_d(const float* __restrict__ WD,
                                                float* __restrict__ out){
    extern __shared__ char smem[];
    int tile = blockIdx.y;
    int e = g_tileE[tile];
    if (e < 0) return;
    int n0 = blockIdx.x*64;
    int m0 = g_tileM[tile]*128;
    int base = g_off[e];
    int Me   = g_off[e+1] - base;
    int tid = threadIdx.x, lane = tid&31, wid = tid>>5;
    uint32_t sb = smem_u32(smem);

    const __half* srcA[2]; uint32_t dofA[2];
    #pragma unroll
    for (int i=0;i<2;i++){
        int c = tid + i*256, row = c>>2, ch = c&3;
        srcA[i] = g_Hbuf16 + (size_t)(base+m0+row)*F_ + ch*8;
        dofA[i] = (uint32_t)row*RSTRIDE + ch*16;
    }
    int rowB = tid>>2, chB = tid&3;
    const float* srcB = WD + (size_t)e*H_*F_ + (size_t)(n0+rowB)*F_ + chB*8;
    uint32_t dofB = (uint32_t)rowB*RSTRIDE + chB*16;

    const int NKT = F_/32;   // 16
    float4 hb0,hb1;
    {
        float4 b0 = *(const float4*)(srcB), b1 = *(const float4*)(srcB+4);
        *(uint4*)(smem + DN_BOFF + dofB) = pack8(b0,b1);
        hb0 = *(const float4*)(srcB+32); hb1 = *(const float4*)(srcB+36);
    }
    #pragma unroll
    for (int kt=0; kt<2; kt++){
        uint32_t s0 = sb + kt*DN_STG;
        cpa16(s0 + dofA[0], srcA[0] + kt*32);
        cpa16(s0 + dofA[1], srcA[1] + kt*32);
        CP_COMMIT();
    }

    int g = lane>>2, tg = lane&3;
    int wm = wid&3, wn = wid>>2;
    uint32_t aOff = (uint32_t)(wm*32 + (lane&7) + ((lane>>3)&1)*8)*RSTRIDE + ((lane>>4)&1)*16;
    uint32_t bOff = (uint32_t)(wn*32 + (lane&7) + ((lane>>4)&1)*8)*RSTRIDE + ((lane>>3)&1)*16;

    float acc[2][4][4] = {};

    for (int kt=0; kt<NKT; kt++){
        CP_WAIT1();
        __syncthreads();
        if (kt+1 < NKT){
            char* st = smem + ((kt+1)%3)*DN_STG;
            *(uint4*)(st + DN_BOFF + dofB) = pack8(hb0,hb1);
        }
        if (kt+2 < NKT){
            int ko = (kt+2)*32;
            hb0 = *(const float4*)(srcB+ko); hb1 = *(const float4*)(srcB+ko+4);
            uint32_t s0 = sb + ((kt+2)%3)*DN_STG;
            cpa16(s0 + dofA[0], srcA[0] + ko);
            cpa16(s0 + dofA[1], srcA[1] + ko);
        }
        CP_COMMIT();
        int s = kt - (kt/3)*3;
        uint32_t sA = sb + s*DN_STG;
        uint32_t sB = sA + DN_BOFF;
        #pragma unroll
        for (int ks=0; ks<2; ks++){
            uint32_t a0[4], a1[4], bb[8];
            ldsm4(a0[0],a0[1],a0[2],a0[3], sA + aOff + ks*32);
            ldsm4(a1[0],a1[1],a1[2],a1[3], sA + aOff + 16*RSTRIDE + ks*32);
            ldsm4(bb[0],bb[1],bb[2],bb[3], sB + bOff + ks*32);
            ldsm4(bb[4],bb[5],bb[6],bb[7], sB + bOff + 16*RSTRIDE + ks*32);
            #pragma unroll
            for (int nf=0; nf<4; nf++){
                mma_f16(acc[0][nf], a0[0],a0[1],a0[2],a0[3], bb[nf*2],bb[nf*2+1]);
                mma_f16(acc[1][nf], a1[0],a1[1],a1[2],a1[3], bb[nf*2],bb[nf*2+1]);
            }
        }
    }

    #pragma unroll
    for (int mt=0; mt<2; mt++){
        #pragma unroll
        for (int half=0; half<2; half++){
            int r = wm*32 + mt*16 + half*8 + g;
            if (m0 + r < Me){
                float wsc = g_slotW[base+m0+r];
                int   tok = g_slotTok[base+m0+r];
                float* orow = out + (size_t)tok*H_ + n0;
                #pragma unroll
                for (int nf=0; nf<4; nf++){
                    int col = wn*32 + nf*8 + 2*tg;
                    atomicAdd(&orow[col  ], acc[mt][nf][half*2  ]*wsc);
                    atomicAdd(&orow[col+1], acc[mt][nf][half*2+1]*wsc);
                }
            }
        }
    }
}

// ---------------- launch ----------------------------------------------------
extern "C" void kernel_launch(void* const* d_in, const int* in_sizes, int n_in,
                              void* d_out, int out_size){
    const float* RI = (const float*)d_in[0];
    const float* HS = (const float*)d_in[1];
    const float* WR = (const float*)d_in[2];
    const float* WG = (const float*)d_in[3];
    const float* WU = (const float*)d_in[4];
    const float* WD = (const float*)d_in[5];
    float* out    = (float*)d_out;
    float* logits = out + (size_t)T_*H_;

    cudaFuncSetAttribute(gateup_d, cudaFuncAttributeMaxDynamicSharedMemorySize, GU_SMEM);
    cudaFuncSetAttribute(down_d,   cudaFuncAttributeMaxDynamicSharedMemorySize, DN_SMEM);

    void* cntp; cudaGetSymbolAddress(&cntp, g_cnt);
    cudaMemsetAsync(out, 0, (size_t)T_*H_*sizeof(float));
    cudaMemsetAsync(cntp, 0, E_*sizeof(int));

    xrouter     <<<128+256, 256>>>((const float4*)HS, RI, WR, logits);
    scanscatter <<<1, 256>>>();
    gateup_d    <<<dim3(F_/64, MAXTILES), 256, GU_SMEM>>>(WG, WU);
    down_d      <<<dim3(H_/64, MAXTILES), 256, DN_SMEM>>>(WD, out);
}